// round 3
// baseline (speedup 1.0000x reference)
#include <cuda_runtime.h>
#include <math.h>

#define ED 1536
#define BN 64
#define TILE_R 16
#define NTHREADS 256
#define XS 1540            // padded X row stride (floats): 1540 % 32 == 4 -> de-conflicted
#define KCD 128            // down-proj k chunk
#define WDS 132            // down W row stride (132 % 32 == 4)
#define DCU 256            // up-proj d chunk
#define WUS 68             // up W row stride (68 % 32 == 4)

// Scratch (allocation-free): gamma-folded down-proj weights + per-b correction scalars
__device__ float g_wdg[BN * ED];
__device__ float g_S1[BN];
__device__ float g_S2[BN];

typedef unsigned long long u64;
__device__ __forceinline__ u64 pk(float a, float b) {
    u64 r; asm("mov.b64 %0, {%1, %2};" : "=l"(r) : "f"(a), "f"(b)); return r;
}
__device__ __forceinline__ void f2fma(u64 &d, u64 a, u64 b) {
    asm("fma.rn.f32x2 %0, %1, %2, %0;" : "+l"(d) : "l"(a), "l"(b));
}
__device__ __forceinline__ float f2sum(u64 a) {
    float x, y; asm("mov.b64 {%0, %1}, %2;" : "=f"(x), "=f"(y) : "l"(a)); return x + y;
}
__device__ __forceinline__ void cp16(float* dst_smem, const float* src) {
    unsigned a = (unsigned)__cvta_generic_to_shared(dst_smem);
    asm volatile("cp.async.cg.shared.global [%0], [%1], 16;\n" :: "r"(a), "l"(src));
}
#define CP_COMMIT() asm volatile("cp.async.commit_group;\n" ::: "memory")
#define CP_WAIT(n)  asm volatile("cp.async.wait_group %0;\n" :: "n"(n) : "memory")

// ---------- prep: wdg = w_down * gamma; S1 = sum(gamma*w); S2 = sum(beta*w)+b_down ----------
__global__ void prep_kernel(const float* __restrict__ w_down,
                            const float* __restrict__ b_down,
                            const float* __restrict__ gamma,
                            const float* __restrict__ beta) {
    int b = blockIdx.x;
    int tid = threadIdx.x;
    float s1 = 0.f, s2 = 0.f;
    for (int k = tid; k < ED; k += blockDim.x) {
        float w = w_down[b * ED + k];
        float wg = w * gamma[k];
        g_wdg[b * ED + k] = wg;
        s1 += wg;
        s2 += beta[k] * w;
    }
    __shared__ float r1[256], r2[256];
    r1[tid] = s1; r2[tid] = s2;
    __syncthreads();
    for (int s = 128; s > 0; s >>= 1) {
        if (tid < s) { r1[tid] += r1[tid + s]; r2[tid] += r2[tid + s]; }
        __syncthreads();
    }
    if (tid == 0) { g_S1[b] = r1[0]; g_S2[b] = r2[0] + b_down[b]; }
}

// smem layout (floats):
//   X  [16][XS]                 24640
//   W  max(2*64*WDS, 256*WUS) = 17408  (down double-buffer / up single)
//   H  [16][64]                  1024
//   P  partials                  4096
//   ST [16][2]                     32
#define SMEM_FLOATS (TILE_R * XS + 17408 + 1024 + 4096 + 32)

__global__ void __launch_bounds__(NTHREADS, 1)
peft_kernel(const float* __restrict__ x,
            const float* __restrict__ w_up,
            const float* __restrict__ b_up,
            float* __restrict__ out) {
    extern __shared__ float smem[];
    float* X  = smem;
    float* W  = smem + TILE_R * XS;
    float* H  = W + 17408;
    float* P  = H + 1024;
    float* ST = P + 4096;

    const int tid  = threadIdx.x;
    const int warp = tid >> 5;
    const int lane = tid & 31;
    const long row0 = (long)blockIdx.x * TILE_R;

    // ---- prologue: async-stage down-W chunk 0 (overlaps with X staging + stats) ----
    {
        #pragma unroll
        for (int n = 0; n < 8; ++n) {
            int idx = tid + n * NTHREADS;
            int bb = idx >> 5, kk4 = idx & 31;
            cp16(W + bb * WDS + kk4 * 4, g_wdg + bb * ED + kk4 * 4);
        }
        CP_COMMIT();
    }

    // ---- stage x tile into smem (coalesced float4, padded rows) ----
    const float4* xg = (const float4*)(x + row0 * ED);
    for (int i = tid; i < TILE_R * ED / 4; i += NTHREADS) {
        int r = i / (ED / 4), c4 = i % (ED / 4);
        *(float4*)(X + r * XS + c4 * 4) = xg[i];
    }
    __syncthreads();

    // ---- LayerNorm stats: 8 warps x 2 rows ----
    for (int rr = 0; rr < 2; ++rr) {
        int r = warp * 2 + rr;
        float s = 0.f, q = 0.f;
        const float4* row = (const float4*)(X + r * XS);
        for (int j = lane; j < ED / 4; j += 32) {
            float4 v = row[j];
            s += v.x + v.y + v.z + v.w;
            q += v.x * v.x + v.y * v.y + v.z * v.z + v.w * v.w;
        }
        for (int o = 16; o; o >>= 1) {
            s += __shfl_xor_sync(0xFFFFFFFFu, s, o);
            q += __shfl_xor_sync(0xFFFFFFFFu, q, o);
        }
        if (lane == 0) {
            float m = s * (1.f / ED);
            float v = q * (1.f / ED) - m * m;
            ST[r * 2]     = m;
            ST[r * 2 + 1] = rsqrtf(v + 1e-5f);
        }
    }

    // ---- down-proj: thread = (kg k-split, rg row-group, bg b-group) ----
    // k-split 4, each thread owns 4 rows x 4 b (b = bg + 16*i), acc packed over k.
    const int kg = tid >> 6;
    const int t  = tid & 63;
    const int rg = t >> 4;
    const int bg = t & 15;

    u64 acc[4][4];
    #pragma unroll
    for (int j = 0; j < 4; ++j)
        #pragma unroll
        for (int i = 0; i < 4; ++i) acc[j][i] = 0ull;

    const int NCH = ED / KCD;  // 12
    for (int c = 0; c < NCH; ++c) {
        if (c + 1 < NCH) {
            float* buf = W + ((c + 1) & 1) * (BN * WDS);
            #pragma unroll
            for (int n = 0; n < 8; ++n) {
                int idx = tid + n * NTHREADS;
                int bb = idx >> 5, kk4 = idx & 31;
                cp16(buf + bb * WDS + kk4 * 4, g_wdg + bb * ED + (c + 1) * KCD + kk4 * 4);
            }
            CP_COMMIT();
            CP_WAIT(1);
        } else {
            CP_WAIT(0);
        }
        __syncthreads();

        const float* Wb = W + (c & 1) * (BN * WDS);
        const float* Xb = X + c * KCD;
        const int k0 = kg * 32;
        #pragma unroll 2
        for (int kk = k0; kk < k0 + 32; kk += 4) {
            u64 w01[4], w23[4];
            #pragma unroll
            for (int i = 0; i < 4; ++i) {
                float4 wv = *(const float4*)(Wb + (bg + i * 16) * WDS + kk);
                w01[i] = pk(wv.x, wv.y); w23[i] = pk(wv.z, wv.w);
            }
            #pragma unroll
            for (int j = 0; j < 4; ++j) {
                float4 xv = *(const float4*)(Xb + (rg * 4 + j) * XS + kk);
                u64 x01 = pk(xv.x, xv.y), x23 = pk(xv.z, xv.w);
                #pragma unroll
                for (int i = 0; i < 4; ++i) {
                    f2fma(acc[j][i], x01, w01[i]);
                    f2fma(acc[j][i], x23, w23[i]);
                }
            }
        }
        __syncthreads();
    }

    // ---- reduce k-split partials, finalize h + exact GELU ----
    #pragma unroll
    for (int j = 0; j < 4; ++j)
        #pragma unroll
        for (int i = 0; i < 4; ++i)
            P[(kg * 64 + t) * 16 + j * 4 + i] = f2sum(acc[j][i]);
    __syncthreads();

    for (int o = tid; o < TILE_R * BN; o += NTHREADS) {
        int r = o >> 6, b = o & 63;
        int t2 = (r >> 2) * 16 + (b & 15);
        int idx = t2 * 16 + (r & 3) * 4 + (b >> 4);
        float val = P[idx] + P[idx + 1024] + P[idx + 2048] + P[idx + 3072];
        float mean = ST[r * 2], rstd = ST[r * 2 + 1];
        float hh = rstd * val - rstd * mean * g_S1[b] + g_S2[b];
        H[r * 64 + b] = 0.5f * hh * (1.f + erff(hh * 0.70710678118654752f));
    }

    // ---- up-proj: thread owns 8 rows x 2 d (d = dgu, dgu+128); acc packed over b ----
    const int rg2 = tid >> 7;          // 2 row-groups of 8 (uniform per warp)
    const int dgu = tid & 127;

    for (int d0 = 0; d0 < ED; d0 += DCU) {
        __syncthreads();               // H ready / prev compute & writeback done
        #pragma unroll
        for (int n = 0; n < 16; ++n) {
            int idx = tid + n * NTHREADS;
            int dl = idx >> 4, b4 = idx & 15;
            cp16(W + dl * WUS + b4 * 4, w_up + (long)(d0 + dl) * BN + b4 * 4);
        }
        CP_COMMIT();
        CP_WAIT(0);
        __syncthreads();

        float bu0 = b_up[d0 + dgu];
        float bu1 = b_up[d0 + dgu + 128];

        u64 acc2[8][2];
        #pragma unroll
        for (int rr = 0; rr < 8; ++rr) { acc2[rr][0] = 0ull; acc2[rr][1] = 0ull; }

        #pragma unroll 4
        for (int bb = 0; bb < BN; bb += 4) {
            float4 wv0 = *(const float4*)(W + dgu * WUS + bb);
            float4 wv1 = *(const float4*)(W + (dgu + 128) * WUS + bb);
            u64 wa0 = pk(wv0.x, wv0.y), wb0 = pk(wv0.z, wv0.w);
            u64 wa1 = pk(wv1.x, wv1.y), wb1 = pk(wv1.z, wv1.w);
            #pragma unroll
            for (int rr = 0; rr < 8; ++rr) {
                float4 hv = *(const float4*)(H + (rg2 * 8 + rr) * 64 + bb);
                u64 h01 = pk(hv.x, hv.y), h23 = pk(hv.z, hv.w);
                f2fma(acc2[rr][0], h01, wa0);
                f2fma(acc2[rr][0], h23, wb0);
                f2fma(acc2[rr][1], h01, wa1);
                f2fma(acc2[rr][1], h23, wb1);
            }
        }

        #pragma unroll
        for (int rr = 0; rr < 8; ++rr) {
            int r = rg2 * 8 + rr;
            float* Xr = X + r * XS + d0;
            float v0 = f2sum(acc2[rr][0]) + bu0 + Xr[dgu];
            float v1 = f2sum(acc2[rr][1]) + bu1 + Xr[dgu + 128];
            Xr[dgu] = v0;
            Xr[dgu + 128] = v1;
        }
    }
    __syncthreads();

    // ---- L2 normalize rows ----
    for (int rr = 0; rr < 2; ++rr) {
        int r = warp * 2 + rr;
        float q = 0.f;
        const float4* row = (const float4*)(X + r * XS);
        for (int j = lane; j < ED / 4; j += 32) {
            float4 v = row[j];
            q += v.x * v.x + v.y * v.y + v.z * v.z + v.w * v.w;
        }
        for (int o = 16; o; o >>= 1) q += __shfl_xor_sync(0xFFFFFFFFu, q, o);
        if (lane == 0) ST[r * 2] = 1.f / fmaxf(sqrtf(q), 1e-12f);
    }
    __syncthreads();

    // ---- scaled write-out (coalesced float4) ----
    float4* og = (float4*)(out + row0 * ED);
    for (int i = tid; i < TILE_R * ED / 4; i += NTHREADS) {
        int r = i / (ED / 4), c4 = i % (ED / 4);
        float sc = ST[r * 2];
        float4 v = *(const float4*)(X + r * XS + c4 * 4);
        v.x *= sc; v.y *= sc; v.z *= sc; v.w *= sc;
        og[i] = v;
    }
}

extern "C" void kernel_launch(void* const* d_in, const int* in_sizes, int n_in,
                              void* d_out, int out_size) {
    const float* x      = (const float*)d_in[0];
    const float* w_down = (const float*)d_in[1];
    const float* b_down = (const float*)d_in[2];
    const float* w_up   = (const float*)d_in[3];
    const float* b_up   = (const float*)d_in[4];
    const float* gamma  = (const float*)d_in[5];
    const float* beta   = (const float*)d_in[6];
    float* out = (float*)d_out;

    const int n_rows = in_sizes[0] / ED;   // 32768

    cudaFuncSetAttribute(peft_kernel, cudaFuncAttributeMaxDynamicSharedMemorySize,
                         SMEM_FLOATS * (int)sizeof(float));

    prep_kernel<<<BN, 256>>>(w_down, b_down, gamma, beta);
    peft_kernel<<<n_rows / TILE_R, NTHREADS, SMEM_FLOATS * sizeof(float)>>>(x, w_up, b_up, out);
}

// round 5
// speedup vs baseline: 2.1982x; 2.1982x over previous
#include <cuda_runtime.h>
#include <cuda_bf16.h>
#include <math.h>

#define ED 1536
#define BN 64
#define MT 64
#define NTH 512

// ---- smem byte offsets (from 1KB-aligned base) ----
#define O_XB(b)  ((b) * 32768)            // X bf16 chunk: hi @+0 (16KB), lo @+16384
#define O_WB(b)  (65536 + (b) * 32768)    // W bf16 chunk: hi @+0 (16KB), lo @+16384
#define O_HH     131072
#define O_HL     139264
#define O_HRAW   147456                    // 64 x 66 fp32
#define O_BU     164352
#define O_S1     170496
#define O_S2     170752
#define O_MS     171008
#define O_RS     171264
#define O_NRM    171520                    // 64 x 17 fp32
#define O_INV    175872
#define SMEM_REQ (176128 + 1024)

__device__ __nv_bfloat16 g_wdh[BN * ED];   // [12 chunks][64 n][128 k]
__device__ __nv_bfloat16 g_wdl[BN * ED];
__device__ __nv_bfloat16 g_wuh[ED * BN];   // [12 chunks][128 d][64 k]
__device__ __nv_bfloat16 g_wul[ED * BN];
__device__ float g_S1[BN], g_S2[BN];

// swizzles: 256B rows (16 units) / 128B rows (8 units)
__device__ __forceinline__ unsigned SWA(unsigned r, unsigned u) {
    return r * 256 + ((((u ^ r) & 7) | (u & 8)) * 16);
}
__device__ __forceinline__ unsigned SWB(unsigned r, unsigned u) {
    return r * 128 + (((u ^ r) & 7) * 16);
}

__device__ __forceinline__ void ldsm4(unsigned* r, unsigned a) {
    asm volatile("ldmatrix.sync.aligned.m8n8.x4.shared.b16 {%0,%1,%2,%3}, [%4];"
                 : "=r"(r[0]), "=r"(r[1]), "=r"(r[2]), "=r"(r[3]) : "r"(a));
}
__device__ __forceinline__ void mma_bf(float* c, const unsigned* a, const unsigned* b) {
    asm volatile("mma.sync.aligned.m16n8k16.row.col.f32.bf16.bf16.f32 "
                 "{%0,%1,%2,%3},{%4,%5,%6,%7},{%8,%9},{%0,%1,%2,%3};"
                 : "+f"(c[0]), "+f"(c[1]), "+f"(c[2]), "+f"(c[3])
                 : "r"(a[0]), "r"(a[1]), "r"(a[2]), "r"(a[3]), "r"(b[0]), "r"(b[1]));
}
__device__ __forceinline__ void cp16(unsigned dst, const void* src) {
    asm volatile("cp.async.cg.shared.global [%0], [%1], 16;" :: "r"(dst), "l"(src));
}
#define CP_COMMIT() asm volatile("cp.async.commit_group;" ::: "memory")
#define CP_WAIT0()  asm volatile("cp.async.wait_group 0;" ::: "memory")

__device__ __forceinline__ void split2(float a, float b, unsigned& h, unsigned& l) {
    __nv_bfloat16 ha = __float2bfloat16_rn(a), hb = __float2bfloat16_rn(b);
    float ra = a - __bfloat162float(ha), rb = b - __bfloat162float(hb);
    __nv_bfloat16 la = __float2bfloat16_rn(ra), lb = __float2bfloat16_rn(rb);
    h = (unsigned)__bfloat16_as_ushort(ha) | ((unsigned)__bfloat16_as_ushort(hb) << 16);
    l = (unsigned)__bfloat16_as_ushort(la) | ((unsigned)__bfloat16_as_ushort(lb) << 16);
}

// ---------- prep ----------
__global__ void prep_down(const float* __restrict__ w_down, const float* __restrict__ b_down,
                          const float* __restrict__ gamma,  const float* __restrict__ beta) {
    int b = blockIdx.x, tid = threadIdx.x;
    float s1 = 0.f, s2 = 0.f;
    for (int k = tid; k < ED; k += 256) {
        float w = w_down[b * ED + k];
        float wg = w * gamma[k];
        s1 += wg; s2 += beta[k] * w;
        __nv_bfloat16 hi = __float2bfloat16_rn(wg);
        __nv_bfloat16 lo = __float2bfloat16_rn(wg - __bfloat162float(hi));
        int idx = (k >> 7) * 8192 + b * 128 + (k & 127);
        g_wdh[idx] = hi; g_wdl[idx] = lo;
    }
    __shared__ float r1[256], r2[256];
    r1[tid] = s1; r2[tid] = s2; __syncthreads();
    for (int s = 128; s > 0; s >>= 1) {
        if (tid < s) { r1[tid] += r1[tid + s]; r2[tid] += r2[tid + s]; }
        __syncthreads();
    }
    if (tid == 0) { g_S1[b] = r1[0]; g_S2[b] = r2[0] + b_down[b]; }
}
__global__ void prep_up(const float* __restrict__ w_up) {
    int c = blockIdx.x, tid = threadIdx.x;
    for (int i = tid; i < 8192; i += 256) {
        int d = i >> 6, k = i & 63;
        float w = w_up[(c * 128 + d) * BN + k];
        __nv_bfloat16 hi = __float2bfloat16_rn(w);
        __nv_bfloat16 lo = __float2bfloat16_rn(w - __bfloat162float(hi));
        g_wuh[c * 8192 + i] = hi; g_wul[c * 8192 + i] = lo;
    }
}

// ---------- main ----------
__global__ void __launch_bounds__(NTH, 1)
peft_mma(const float* __restrict__ x, const float* __restrict__ bup, float* __restrict__ out) {
    extern __shared__ char smraw[];
    unsigned rawa = (unsigned)__cvta_generic_to_shared(smraw);
    unsigned sa = (rawa + 1023) & ~1023u;
    char* sb = smraw + (sa - rawa);

    const int tid = threadIdx.x, warp = tid >> 5, lane = tid & 31;
    const int m = warp & 3, nq = warp >> 2;      // m-tile, n-quarter
    const long row0 = (long)blockIdx.x * MT;
    const int cr = tid >> 3, cs = tid & 7;       // conversion row / segment

    float* BU  = (float*)(sb + O_BU);
    float* S1s = (float*)(sb + O_S1);
    float* S2s = (float*)(sb + O_S2);

    for (int i = tid; i < ED; i += NTH) BU[i] = bup[i];
    if (tid < BN) { S1s[tid] = g_S1[tid]; S2s[tid] = g_S2[tid]; }

    float sum = 0.f, sq = 0.f;

    // ---- prologue: stage Wd chunk 0 + convert X chunk 0 ----
    {
        #pragma unroll
        for (int s = 0; s < 2; ++s) {
            int i = tid * 2 + s, n = i >> 4, u = i & 15;
            cp16(sa + O_WB(0) + SWA(n, u),         g_wdh + n * 128 + u * 8);
            cp16(sa + O_WB(0) + 16384 + SWA(n, u), g_wdl + n * 128 + u * 8);
        }
        CP_COMMIT();
    }
    {
        const float* xp = x + (row0 + cr) * ED;
        char* xb = sb + O_XB(0);
        #pragma unroll
        for (int j = 0; j < 4; ++j) {
            float4 v = *(const float4*)(xp + j * 32 + cs * 4);
            sum += v.x + v.y + v.z + v.w;
            sq  += v.x * v.x + v.y * v.y + v.z * v.z + v.w * v.w;
            unsigned h0, l0, h1, l1;
            split2(v.x, v.y, h0, l0); split2(v.z, v.w, h1, l1);
            unsigned off = SWA(cr, j * 4 + (cs >> 1)) + (cs & 1) * 8;
            *(uint2*)(xb + off)         = make_uint2(h0, h1);
            *(uint2*)(xb + 16384 + off) = make_uint2(l0, l1);
        }
    }

    // ================= GEMM1: H[64,64] = X * (gamma*Wd)^T =================
    float C1[2][8];
    #pragma unroll
    for (int nt = 0; nt < 2; ++nt)
        #pragma unroll
        for (int i = 0; i < 8; ++i) C1[nt][i] = 0.f;  // flatten [2][2][4] -> [2][8]

    for (int c = 0; c < 12; ++c) {
        CP_WAIT0();
        __syncthreads();
        if (c < 11) {
            #pragma unroll
            for (int s = 0; s < 2; ++s) {
                int i = tid * 2 + s, n = i >> 4, u = i & 15;
                cp16(sa + O_WB((c + 1) & 1) + SWA(n, u),         g_wdh + (c + 1) * 8192 + n * 128 + u * 8);
                cp16(sa + O_WB((c + 1) & 1) + 16384 + SWA(n, u), g_wdl + (c + 1) * 8192 + n * 128 + u * 8);
            }
            CP_COMMIT();
        }
        unsigned xb = sa + O_XB(c & 1);
        unsigned wb = sa + O_WB(c & 1);
        const unsigned rowA = m * 16 + (lane & 15);
        #pragma unroll
        for (int kp = 0; kp < 8; kp += 2) {
            unsigned ah0[4], al0[4], ah1[4], al1[4];
            unsigned uA0 = 2 * kp + (lane >> 4), uA1 = uA0 + 2;
            ldsm4(ah0, xb + SWA(rowA, uA0));
            ldsm4(al0, xb + 16384 + SWA(rowA, uA0));
            ldsm4(ah1, xb + SWA(rowA, uA1));
            ldsm4(al1, xb + 16384 + SWA(rowA, uA1));
            #pragma unroll
            for (int nt = 0; nt < 2; ++nt) {
                unsigned bh[4], bl[4];
                unsigned rowB = nq * 16 + nt * 8 + (lane & 7);
                unsigned uB = 2 * kp + (lane >> 3);
                ldsm4(bh, wb + SWA(rowB, uB));
                ldsm4(bl, wb + 16384 + SWA(rowB, uB));
                float* Cp = C1[nt];
                mma_bf(Cp, ah0, bh);     mma_bf(Cp, al0, bh);     mma_bf(Cp, ah0, bl);
                mma_bf(Cp, ah1, bh + 2); mma_bf(Cp, al1, bh + 2); mma_bf(Cp, ah1, bl + 2);
                (void)Cp;
            }
        }
        if (c < 11) {
            const float* xp = x + (row0 + cr) * ED + (c + 1) * 128;
            char* xcb = sb + O_XB((c + 1) & 1);
            #pragma unroll
            for (int j = 0; j < 4; ++j) {
                float4 v = *(const float4*)(xp + j * 32 + cs * 4);
                sum += v.x + v.y + v.z + v.w;
                sq  += v.x * v.x + v.y * v.y + v.z * v.z + v.w * v.w;
                unsigned h0, l0, h1, l1;
                split2(v.x, v.y, h0, l0); split2(v.z, v.w, h1, l1);
                unsigned off = SWA(cr, j * 4 + (cs >> 1)) + (cs & 1) * 8;
                *(uint2*)(xcb + off)         = make_uint2(h0, h1);
                *(uint2*)(xcb + 16384 + off) = make_uint2(l0, l1);
            }
        }
    }

    // ---- LN stats (8 threads per row, same warp) ----
    #pragma unroll
    for (int o = 1; o < 8; o <<= 1) {
        sum += __shfl_xor_sync(0xFFFFFFFFu, sum, o);
        sq  += __shfl_xor_sync(0xFFFFFFFFu, sq,  o);
    }
    if (cs == 0) {
        float mean = sum * (1.f / ED);
        ((float*)(sb + O_MS))[cr] = mean;
        ((float*)(sb + O_RS))[cr] = rsqrtf(sq * (1.f / ED) - mean * mean + 1e-5f);
    }

    // ---- write C1 frags -> Hraw ----
    {
        float* Hr = (float*)(sb + O_HRAW);
        #pragma unroll
        for (int nt = 0; nt < 2; ++nt)
            #pragma unroll
            for (int h = 0; h < 2; ++h) {
                int row = m * 16 + (lane >> 2) + h * 8;
                int col = nq * 16 + nt * 8 + 2 * (lane & 3);
                *(float2*)(Hr + row * 66 + col) = make_float2(C1[nt][h * 2], C1[nt][h * 2 + 1]);
            }
    }
    __syncthreads();

    // ---- LN finalize + GELU + bf16 split -> HH/HL ----
    {
        const float* Hr = (const float*)(sb + O_HRAW);
        int r = tid >> 3, u = tid & 7;
        float mean = ((float*)(sb + O_MS))[r], rstd = ((float*)(sb + O_RS))[r];
        unsigned hw[4], lw[4];
        #pragma unroll
        for (int p = 0; p < 4; ++p) {
            int c0 = u * 8 + p * 2;
            float v0 = Hr[r * 66 + c0], v1 = Hr[r * 66 + c0 + 1];
            float t0 = rstd * v0 - rstd * mean * S1s[c0]     + S2s[c0];
            float t1 = rstd * v1 - rstd * mean * S1s[c0 + 1] + S2s[c0 + 1];
            float g0 = 0.5f * t0 * (1.f + erff(t0 * 0.70710678118654752f));
            float g1 = 0.5f * t1 * (1.f + erff(t1 * 0.70710678118654752f));
            split2(g0, g1, hw[p], lw[p]);
        }
        *(uint4*)(sb + O_HH + SWB(r, u)) = make_uint4(hw[0], hw[1], hw[2], hw[3]);
        *(uint4*)(sb + O_HL + SWB(r, u)) = make_uint4(lw[0], lw[1], lw[2], lw[3]);
    }
    __syncthreads();

    // ================= GEMM2: out = H * Wu^T + b_up + x =================
    unsigned Ah[4][4], Al[4][4];
    {
        unsigned rowA = m * 16 + (lane & 15);
        #pragma unroll
        for (int kk = 0; kk < 4; ++kk) {
            unsigned uA = 2 * kk + (lane >> 4);
            ldsm4(Ah[kk], sa + O_HH + SWB(rowA, uA));
            ldsm4(Al[kk], sa + O_HL + SWB(rowA, uA));
        }
    }
    // stage Wu chunk 0
    {
        #pragma unroll
        for (int s = 0; s < 2; ++s) {
            int i = tid * 2 + s, d = i >> 3, u = i & 7;
            cp16(sa + O_WB(0) + SWB(d, u),         g_wuh + d * 64 + u * 8);
            cp16(sa + O_WB(0) + 16384 + SWB(d, u), g_wul + d * 64 + u * 8);
        }
        CP_COMMIT();
    }

    float nacc0 = 0.f, nacc1 = 0.f;
    for (int c = 0; c < 12; ++c) {
        CP_WAIT0();
        __syncthreads();
        if (c < 11) {
            #pragma unroll
            for (int s = 0; s < 2; ++s) {
                int i = tid * 2 + s, d = i >> 3, u = i & 7;
                cp16(sa + O_WB((c + 1) & 1) + SWB(d, u),         g_wuh + (c + 1) * 8192 + d * 64 + u * 8);
                cp16(sa + O_WB((c + 1) & 1) + 16384 + SWB(d, u), g_wul + (c + 1) * 8192 + d * 64 + u * 8);
            }
            CP_COMMIT();
        }
        unsigned wb = sa + O_WB(c & 1);
        #pragma unroll
        for (int nt = 0; nt < 4; ++nt) {
            float C2[4] = {0.f, 0.f, 0.f, 0.f};
            unsigned bh[2][4], bl[2][4];
            unsigned rowB = nq * 32 + nt * 8 + (lane & 7);
            #pragma unroll
            for (int kp = 0; kp < 2; ++kp) {
                unsigned uB = 4 * kp + (lane >> 3);
                ldsm4(bh[kp], wb + SWB(rowB, uB));
                ldsm4(bl[kp], wb + 16384 + SWB(rowB, uB));
            }
            #pragma unroll
            for (int kk = 0; kk < 4; ++kk) {
                const unsigned* bhp = &bh[kk >> 1][(kk & 1) * 2];
                const unsigned* blp = &bl[kk >> 1][(kk & 1) * 2];
                mma_bf(C2, Ah[kk], bhp);
                mma_bf(C2, Al[kk], bhp);
                mma_bf(C2, Ah[kk], blp);
            }
            // epilogue: + b_up + residual, direct STG
            int col = c * 128 + nq * 32 + nt * 8 + 2 * (lane & 3);
            {
                long rg = row0 + m * 16 + (lane >> 2);
                float2 xr = *(const float2*)(x + rg * ED + col);
                float v0 = C2[0] + xr.x + BU[col];
                float v1 = C2[1] + xr.y + BU[col + 1];
                nacc0 += v0 * v0 + v1 * v1;
                *(float2*)(out + rg * ED + col) = make_float2(v0, v1);
            }
            {
                long rg = row0 + m * 16 + 8 + (lane >> 2);
                float2 xr = *(const float2*)(x + rg * ED + col);
                float v2 = C2[2] + xr.x + BU[col];
                float v3 = C2[3] + xr.y + BU[col + 1];
                nacc1 += v2 * v2 + v3 * v3;
                *(float2*)(out + rg * ED + col) = make_float2(v2, v3);
            }
        }
    }

    // ---- row sumsq reduce -> inv norm ----
    {
        float* NR = (float*)(sb + O_NRM);
        NR[(m * 16 + (lane >> 2)) * 17 + nq * 4 + (lane & 3)]     = nacc0;
        NR[(m * 16 + 8 + (lane >> 2)) * 17 + nq * 4 + (lane & 3)] = nacc1;
    }
    __syncthreads();
    if (tid < MT) {
        const float* NR = (const float*)(sb + O_NRM) + tid * 17;
        float s = 0.f;
        #pragma unroll
        for (int i = 0; i < 16; ++i) s += NR[i];
        ((float*)(sb + O_INV))[tid] = 1.f / fmaxf(sqrtf(s), 1e-12f);
    }
    __syncthreads();

    // ---- rescale (L2-hot re-read of this CTA's output) ----
    {
        float sc = ((float*)(sb + O_INV))[cr];
        float4* op = (float4*)(out + (row0 + cr) * ED);
        #pragma unroll 4
        for (int j = 0; j < 48; ++j) {
            float4 v = op[j * 8 + cs];
            v.x *= sc; v.y *= sc; v.z *= sc; v.w *= sc;
            op[j * 8 + cs] = v;
        }
    }
}

extern "C" void kernel_launch(void* const* d_in, const int* in_sizes, int n_in,
                              void* d_out, int out_size) {
    const float* x      = (const float*)d_in[0];
    const float* w_down = (const float*)d_in[1];
    const float* b_down = (const float*)d_in[2];
    const float* w_up   = (const float*)d_in[3];
    const float* b_up   = (const float*)d_in[4];
    const float* gamma  = (const float*)d_in[5];
    const float* beta   = (const float*)d_in[6];
    float* out = (float*)d_out;

    const int n_rows = in_sizes[0] / ED;   // 32768

    cudaFuncSetAttribute(peft_mma, cudaFuncAttributeMaxDynamicSharedMemorySize, SMEM_REQ);

    prep_down<<<BN, 256>>>(w_down, b_down, gamma, beta);
    prep_up<<<12, 256>>>(w_up);
    peft_mma<<<n_rows / MT, NTH, SMEM_REQ>>>(x, b_up, out);
}

// round 6
// speedup vs baseline: 2.3874x; 1.0861x over previous
#include <cuda_runtime.h>
#include <cuda_bf16.h>
#include <math.h>

#define ED 1536
#define BN 64
#define MT 64
#define NTH 512

// ---- smem byte offsets (from 1KB-aligned base) ----
#define O_XB(b)  ((b) * 32768)            // X bf16 chunk: hi @+0 (16KB), lo @+16384
#define O_WB(b)  (65536 + (b) * 32768)    // W bf16 chunk: hi @+0 (16KB), lo @+16384
#define O_HH     131072
#define O_HL     139264
#define O_HRAW   147456                    // 64 x 66 fp32
#define O_BU     164352
#define O_S1     170496
#define O_S2     170752
#define O_MS     171008
#define O_RS     171264
#define O_NRM    171520                    // 64 x 17 fp32
#define O_INV    175872
#define SMEM_REQ (176128 + 1024)

__device__ __nv_bfloat16 g_wdh[BN * ED];   // [12 chunks][64 n][128 k]
__device__ __nv_bfloat16 g_wdl[BN * ED];
__device__ __nv_bfloat16 g_wuh[ED * BN];   // [12 chunks][128 d][64 k]
__device__ __nv_bfloat16 g_wul[ED * BN];
__device__ float g_S1[BN], g_S2[BN];

// swizzles: 256B rows (16 units) / 128B rows (8 units)
__device__ __forceinline__ unsigned SWA(unsigned r, unsigned u) {
    return r * 256 + ((((u ^ r) & 7) | (u & 8)) * 16);
}
__device__ __forceinline__ unsigned SWB(unsigned r, unsigned u) {
    return r * 128 + (((u ^ r) & 7) * 16);
}

__device__ __forceinline__ void ldsm4(unsigned* r, unsigned a) {
    asm volatile("ldmatrix.sync.aligned.m8n8.x4.shared.b16 {%0,%1,%2,%3}, [%4];"
                 : "=r"(r[0]), "=r"(r[1]), "=r"(r[2]), "=r"(r[3]) : "r"(a));
}
__device__ __forceinline__ void mma_bf(float* c, const unsigned* a, const unsigned* b) {
    asm volatile("mma.sync.aligned.m16n8k16.row.col.f32.bf16.bf16.f32 "
                 "{%0,%1,%2,%3},{%4,%5,%6,%7},{%8,%9},{%0,%1,%2,%3};"
                 : "+f"(c[0]), "+f"(c[1]), "+f"(c[2]), "+f"(c[3])
                 : "r"(a[0]), "r"(a[1]), "r"(a[2]), "r"(a[3]), "r"(b[0]), "r"(b[1]));
}
__device__ __forceinline__ void cp16(unsigned dst, const void* src) {
    asm volatile("cp.async.cg.shared.global [%0], [%1], 16;" :: "r"(dst), "l"(src));
}
#define CP_COMMIT() asm volatile("cp.async.commit_group;" ::: "memory")
#define CP_WAIT0()  asm volatile("cp.async.wait_group 0;" ::: "memory")

__device__ __forceinline__ void split2(float a, float b, unsigned& h, unsigned& l) {
    __nv_bfloat16 ha = __float2bfloat16_rn(a), hb = __float2bfloat16_rn(b);
    float ra = a - __bfloat162float(ha), rb = b - __bfloat162float(hb);
    __nv_bfloat16 la = __float2bfloat16_rn(ra), lb = __float2bfloat16_rn(rb);
    h = (unsigned)__bfloat16_as_ushort(ha) | ((unsigned)__bfloat16_as_ushort(hb) << 16);
    l = (unsigned)__bfloat16_as_ushort(la) | ((unsigned)__bfloat16_as_ushort(lb) << 16);
}

// ---------- merged prep: blocks 0..63 do w_down row b; blocks 64..75 do w_up chunk ----------
__global__ void prep_all(const float* __restrict__ w_down, const float* __restrict__ b_down,
                         const float* __restrict__ gamma,  const float* __restrict__ beta,
                         const float* __restrict__ w_up) {
    int tid = threadIdx.x;
    if (blockIdx.x < 64) {
        int b = blockIdx.x;
        float s1 = 0.f, s2 = 0.f;
        for (int k = tid; k < ED; k += 256) {
            float w = w_down[b * ED + k];
            float wg = w * gamma[k];
            s1 += wg; s2 += beta[k] * w;
            __nv_bfloat16 hi = __float2bfloat16_rn(wg);
            __nv_bfloat16 lo = __float2bfloat16_rn(wg - __bfloat162float(hi));
            int idx = (k >> 7) * 8192 + b * 128 + (k & 127);
            g_wdh[idx] = hi; g_wdl[idx] = lo;
        }
        __shared__ float r1[256], r2[256];
        r1[tid] = s1; r2[tid] = s2; __syncthreads();
        for (int s = 128; s > 0; s >>= 1) {
            if (tid < s) { r1[tid] += r1[tid + s]; r2[tid] += r2[tid + s]; }
            __syncthreads();
        }
        if (tid == 0) { g_S1[b] = r1[0]; g_S2[b] = r2[0] + b_down[b]; }
    } else {
        int c = blockIdx.x - 64;
        for (int i = tid; i < 8192; i += 256) {
            int d = i >> 6, k = i & 63;
            float w = w_up[(c * 128 + d) * BN + k];
            __nv_bfloat16 hi = __float2bfloat16_rn(w);
            __nv_bfloat16 lo = __float2bfloat16_rn(w - __bfloat162float(hi));
            g_wuh[c * 8192 + i] = hi; g_wul[c * 8192 + i] = lo;
        }
    }
}

// ---------- main ----------
__global__ void __launch_bounds__(NTH, 1)
peft_mma(const float* __restrict__ x, const float* __restrict__ bup, float* __restrict__ out) {
    extern __shared__ char smraw[];
    unsigned rawa = (unsigned)__cvta_generic_to_shared(smraw);
    unsigned sa = (rawa + 1023) & ~1023u;
    char* sb = smraw + (sa - rawa);

    const int tid = threadIdx.x, warp = tid >> 5, lane = tid & 31;
    const int m = warp & 3, nq = warp >> 2;      // m-tile, n-quarter
    const long row0 = (long)blockIdx.x * MT;
    const int cr = tid >> 3, cs = tid & 7;       // conversion row / segment

    float* BU  = (float*)(sb + O_BU);
    float* S1s = (float*)(sb + O_S1);
    float* S2s = (float*)(sb + O_S2);

    for (int i = tid; i < ED; i += NTH) BU[i] = bup[i];
    if (tid < BN) { S1s[tid] = g_S1[tid]; S2s[tid] = g_S2[tid]; }

    float sum = 0.f, sq = 0.f;

    // ---- prologue: stage Wd chunk 0 + convert X chunk 0 (direct) ----
    {
        #pragma unroll
        for (int s = 0; s < 2; ++s) {
            int i = tid * 2 + s, n = i >> 4, u = i & 15;
            cp16(sa + O_WB(0) + SWA(n, u),         g_wdh + n * 128 + u * 8);
            cp16(sa + O_WB(0) + 16384 + SWA(n, u), g_wdl + n * 128 + u * 8);
        }
        CP_COMMIT();
    }
    {
        const float* xp = x + (row0 + cr) * ED;
        char* xb = sb + O_XB(0);
        #pragma unroll
        for (int j = 0; j < 4; ++j) {
            float4 v = *(const float4*)(xp + j * 32 + cs * 4);
            sum += v.x + v.y + v.z + v.w;
            sq  += v.x * v.x + v.y * v.y + v.z * v.z + v.w * v.w;
            unsigned h0, l0, h1, l1;
            split2(v.x, v.y, h0, l0); split2(v.z, v.w, h1, l1);
            unsigned off = SWA(cr, j * 4 + (cs >> 1)) + (cs & 1) * 8;
            *(uint2*)(xb + off)         = make_uint2(h0, h1);
            *(uint2*)(xb + 16384 + off) = make_uint2(l0, l1);
        }
    }

    // ================= GEMM1: H[64,64] = X * (gamma*Wd)^T =================
    float C1[2][8];
    #pragma unroll
    for (int nt = 0; nt < 2; ++nt)
        #pragma unroll
        for (int i = 0; i < 8; ++i) C1[nt][i] = 0.f;

    float4 pf[4];
    for (int c = 0; c < 12; ++c) {
        CP_WAIT0();
        __syncthreads();
        if (c < 11) {
            #pragma unroll
            for (int s = 0; s < 2; ++s) {
                int i = tid * 2 + s, n = i >> 4, u = i & 15;
                cp16(sa + O_WB((c + 1) & 1) + SWA(n, u),         g_wdh + (c + 1) * 8192 + n * 128 + u * 8);
                cp16(sa + O_WB((c + 1) & 1) + 16384 + SWA(n, u), g_wdl + (c + 1) * 8192 + n * 128 + u * 8);
            }
            CP_COMMIT();
            // register-prefetch x chunk c+1 (latency hidden under MMA block)
            const float* xp = x + (row0 + cr) * ED + (c + 1) * 128;
            #pragma unroll
            for (int j = 0; j < 4; ++j) pf[j] = *(const float4*)(xp + j * 32 + cs * 4);
        }
        unsigned xb = sa + O_XB(c & 1);
        unsigned wb = sa + O_WB(c & 1);
        const unsigned rowA = m * 16 + (lane & 15);
        #pragma unroll
        for (int kp = 0; kp < 8; kp += 2) {
            unsigned ah0[4], al0[4], ah1[4], al1[4];
            unsigned uA0 = 2 * kp + (lane >> 4), uA1 = uA0 + 2;
            ldsm4(ah0, xb + SWA(rowA, uA0));
            ldsm4(al0, xb + 16384 + SWA(rowA, uA0));
            ldsm4(ah1, xb + SWA(rowA, uA1));
            ldsm4(al1, xb + 16384 + SWA(rowA, uA1));
            #pragma unroll
            for (int nt = 0; nt < 2; ++nt) {
                unsigned bh[4], bl[4];
                unsigned rowB = nq * 16 + nt * 8 + (lane & 7);
                unsigned uB = 2 * kp + (lane >> 3);
                ldsm4(bh, wb + SWA(rowB, uB));
                ldsm4(bl, wb + 16384 + SWA(rowB, uB));
                float* Cp = C1[nt];
                mma_bf(Cp, ah0, bh);     mma_bf(Cp, al0, bh);     mma_bf(Cp, ah0, bl);
                mma_bf(Cp, ah1, bh + 2); mma_bf(Cp, al1, bh + 2); mma_bf(Cp, ah1, bl + 2);
            }
        }
        if (c < 11) {
            char* xcb = sb + O_XB((c + 1) & 1);
            #pragma unroll
            for (int j = 0; j < 4; ++j) {
                float4 v = pf[j];
                sum += v.x + v.y + v.z + v.w;
                sq  += v.x * v.x + v.y * v.y + v.z * v.z + v.w * v.w;
                unsigned h0, l0, h1, l1;
                split2(v.x, v.y, h0, l0); split2(v.z, v.w, h1, l1);
                unsigned off = SWA(cr, j * 4 + (cs >> 1)) + (cs & 1) * 8;
                *(uint2*)(xcb + off)         = make_uint2(h0, h1);
                *(uint2*)(xcb + 16384 + off) = make_uint2(l0, l1);
            }
        }
    }

    // ---- LN stats (8 threads per row, same warp) ----
    #pragma unroll
    for (int o = 1; o < 8; o <<= 1) {
        sum += __shfl_xor_sync(0xFFFFFFFFu, sum, o);
        sq  += __shfl_xor_sync(0xFFFFFFFFu, sq,  o);
    }
    if (cs == 0) {
        float mean = sum * (1.f / ED);
        ((float*)(sb + O_MS))[cr] = mean;
        ((float*)(sb + O_RS))[cr] = rsqrtf(sq * (1.f / ED) - mean * mean + 1e-5f);
    }

    // ---- write C1 frags -> Hraw ----
    {
        float* Hr = (float*)(sb + O_HRAW);
        #pragma unroll
        for (int nt = 0; nt < 2; ++nt)
            #pragma unroll
            for (int h = 0; h < 2; ++h) {
                int row = m * 16 + (lane >> 2) + h * 8;
                int col = nq * 16 + nt * 8 + 2 * (lane & 3);
                *(float2*)(Hr + row * 66 + col) = make_float2(C1[nt][h * 2], C1[nt][h * 2 + 1]);
            }
    }
    __syncthreads();

    // ---- LN finalize + GELU + bf16 split -> HH/HL ----
    {
        const float* Hr = (const float*)(sb + O_HRAW);
        int r = tid >> 3, u = tid & 7;
        float mean = ((float*)(sb + O_MS))[r], rstd = ((float*)(sb + O_RS))[r];
        unsigned hw[4], lw[4];
        #pragma unroll
        for (int p = 0; p < 4; ++p) {
            int c0 = u * 8 + p * 2;
            float v0 = Hr[r * 66 + c0], v1 = Hr[r * 66 + c0 + 1];
            float t0 = rstd * v0 - rstd * mean * S1s[c0]     + S2s[c0];
            float t1 = rstd * v1 - rstd * mean * S1s[c0 + 1] + S2s[c0 + 1];
            float g0 = 0.5f * t0 * (1.f + erff(t0 * 0.70710678118654752f));
            float g1 = 0.5f * t1 * (1.f + erff(t1 * 0.70710678118654752f));
            split2(g0, g1, hw[p], lw[p]);
        }
        *(uint4*)(sb + O_HH + SWB(r, u)) = make_uint4(hw[0], hw[1], hw[2], hw[3]);
        *(uint4*)(sb + O_HL + SWB(r, u)) = make_uint4(lw[0], lw[1], lw[2], lw[3]);
    }
    __syncthreads();

    // ================= GEMM2: out = H * Wu^T + b_up + x =================
    unsigned Ah[4][4], Al[4][4];
    {
        unsigned rowA = m * 16 + (lane & 15);
        #pragma unroll
        for (int kk = 0; kk < 4; ++kk) {
            unsigned uA = 2 * kk + (lane >> 4);
            ldsm4(Ah[kk], sa + O_HH + SWB(rowA, uA));
            ldsm4(Al[kk], sa + O_HL + SWB(rowA, uA));
        }
    }
    // stage Wu chunk 0
    {
        #pragma unroll
        for (int s = 0; s < 2; ++s) {
            int i = tid * 2 + s, d = i >> 3, u = i & 7;
            cp16(sa + O_WB(0) + SWB(d, u),         g_wuh + d * 64 + u * 8);
            cp16(sa + O_WB(0) + 16384 + SWB(d, u), g_wul + d * 64 + u * 8);
        }
        CP_COMMIT();
    }

    const long rgA = row0 + m * 16 + (lane >> 2);
    const long rgB = rgA + 8;
    float nacc0 = 0.f, nacc1 = 0.f;
    for (int c = 0; c < 12; ++c) {
        CP_WAIT0();
        __syncthreads();
        // register-prefetch residual x for this chunk's epilogue
        float2 pfr[4][2];
        #pragma unroll
        for (int nt = 0; nt < 4; ++nt) {
            int col = c * 128 + nq * 32 + nt * 8 + 2 * (lane & 3);
            pfr[nt][0] = *(const float2*)(x + rgA * ED + col);
            pfr[nt][1] = *(const float2*)(x + rgB * ED + col);
        }
        if (c < 11) {
            #pragma unroll
            for (int s = 0; s < 2; ++s) {
                int i = tid * 2 + s, d = i >> 3, u = i & 7;
                cp16(sa + O_WB((c + 1) & 1) + SWB(d, u),         g_wuh + (c + 1) * 8192 + d * 64 + u * 8);
                cp16(sa + O_WB((c + 1) & 1) + 16384 + SWB(d, u), g_wul + (c + 1) * 8192 + d * 64 + u * 8);
            }
            CP_COMMIT();
        }
        unsigned wb = sa + O_WB(c & 1);
        #pragma unroll
        for (int nt = 0; nt < 4; ++nt) {
            float C2[4] = {0.f, 0.f, 0.f, 0.f};
            unsigned bh[2][4], bl[2][4];
            unsigned rowB = nq * 32 + nt * 8 + (lane & 7);
            #pragma unroll
            for (int kp = 0; kp < 2; ++kp) {
                unsigned uB = 4 * kp + (lane >> 3);
                ldsm4(bh[kp], wb + SWB(rowB, uB));
                ldsm4(bl[kp], wb + 16384 + SWB(rowB, uB));
            }
            #pragma unroll
            for (int kk = 0; kk < 4; ++kk) {
                const unsigned* bhp = &bh[kk >> 1][(kk & 1) * 2];
                const unsigned* blp = &bl[kk >> 1][(kk & 1) * 2];
                mma_bf(C2, Ah[kk], bhp);
                mma_bf(C2, Al[kk], bhp);
                mma_bf(C2, Ah[kk], blp);
            }
            int col = c * 128 + nq * 32 + nt * 8 + 2 * (lane & 3);
            {
                float v0 = C2[0] + pfr[nt][0].x + BU[col];
                float v1 = C2[1] + pfr[nt][0].y + BU[col + 1];
                nacc0 += v0 * v0 + v1 * v1;
                *(float2*)(out + rgA * ED + col) = make_float2(v0, v1);
            }
            {
                float v2 = C2[2] + pfr[nt][1].x + BU[col];
                float v3 = C2[3] + pfr[nt][1].y + BU[col + 1];
                nacc1 += v2 * v2 + v3 * v3;
                *(float2*)(out + rgB * ED + col) = make_float2(v2, v3);
            }
        }
    }

    // ---- row sumsq reduce -> inv norm ----
    {
        float* NR = (float*)(sb + O_NRM);
        NR[(m * 16 + (lane >> 2)) * 17 + nq * 4 + (lane & 3)]     = nacc0;
        NR[(m * 16 + 8 + (lane >> 2)) * 17 + nq * 4 + (lane & 3)] = nacc1;
    }
    __syncthreads();
    if (tid < MT) {
        const float* NR = (const float*)(sb + O_NRM) + tid * 17;
        float s = 0.f;
        #pragma unroll
        for (int i = 0; i < 16; ++i) s += NR[i];
        ((float*)(sb + O_INV))[tid] = 1.f / fmaxf(sqrtf(s), 1e-12f);
    }
    __syncthreads();

    // ---- rescale (L2-hot re-read of this CTA's output) ----
    {
        float sc = ((float*)(sb + O_INV))[cr];
        float4* op = (float4*)(out + (row0 + cr) * ED);
        #pragma unroll 8
        for (int j = 0; j < 48; ++j) {
            float4 v = op[j * 8 + cs];
            v.x *= sc; v.y *= sc; v.z *= sc; v.w *= sc;
            op[j * 8 + cs] = v;
        }
    }
}

extern "C" void kernel_launch(void* const* d_in, const int* in_sizes, int n_in,
                              void* d_out, int out_size) {
    const float* x      = (const float*)d_in[0];
    const float* w_down = (const float*)d_in[1];
    const float* b_down = (const float*)d_in[2];
    const float* w_up   = (const float*)d_in[3];
    const float* b_up   = (const float*)d_in[4];
    const float* gamma  = (const float*)d_in[5];
    const float* beta   = (const float*)d_in[6];
    float* out = (float*)d_out;

    const int n_rows = in_sizes[0] / ED;   // 32768

    cudaFuncSetAttribute(peft_mma, cudaFuncAttributeMaxDynamicSharedMemorySize, SMEM_REQ);

    prep_all<<<76, 256>>>(w_down, b_down, gamma, beta, w_up);
    peft_mma<<<n_rows / MT, NTH, SMEM_REQ>>>(x, b_up, out);
}

// round 7
// speedup vs baseline: 2.4466x; 1.0248x over previous
#include <cuda_runtime.h>
#include <cuda_bf16.h>
#include <math.h>

#define ED 1536
#define BN 64
#define MT 64
#define NTH 256
#define NCH 24

// ---- smem byte offsets (from 1KB-aligned base) ----
#define O_XB(b)  ((b) * 16384)            // X chunk: hi @+0 (8KB), lo @+8192
#define O_WB(b)  (32768 + (b) * 16384)    // W chunk: hi @+0, lo @+8192
#define O_HH     65536
#define O_HL     73728
#define O_HRAW   0                        // overlay on XB region (64 x 66 fp32 = 16.9KB)
#define O_BU     81920
#define O_S1     88064
#define O_S2     88320
#define O_MS     88576
#define O_RS     88832
#define O_NRM    89088                    // 64 x 9 fp32
#define O_INV    91392
#define SMEM_REQ (91648 + 1024)

__device__ __nv_bfloat16 g_wdh[BN * ED];   // [24][64 n][64 k]
__device__ __nv_bfloat16 g_wdl[BN * ED];
__device__ __nv_bfloat16 g_wuh[ED * BN];   // [24][64 d][64 k]
__device__ __nv_bfloat16 g_wul[ED * BN];
__device__ float g_S1[BN], g_S2[BN];

// 128B rows, 8 units of 16B, XOR swizzle
__device__ __forceinline__ unsigned SWB(unsigned r, unsigned u) {
    return r * 128 + (((u ^ r) & 7) * 16);
}

__device__ __forceinline__ void ldsm4(unsigned* r, unsigned a) {
    asm volatile("ldmatrix.sync.aligned.m8n8.x4.shared.b16 {%0,%1,%2,%3}, [%4];"
                 : "=r"(r[0]), "=r"(r[1]), "=r"(r[2]), "=r"(r[3]) : "r"(a));
}
__device__ __forceinline__ void mma_bf(float* c, const unsigned* a, const unsigned* b) {
    asm volatile("mma.sync.aligned.m16n8k16.row.col.f32.bf16.bf16.f32 "
                 "{%0,%1,%2,%3},{%4,%5,%6,%7},{%8,%9},{%0,%1,%2,%3};"
                 : "+f"(c[0]), "+f"(c[1]), "+f"(c[2]), "+f"(c[3])
                 : "r"(a[0]), "r"(a[1]), "r"(a[2]), "r"(a[3]), "r"(b[0]), "r"(b[1]));
}
__device__ __forceinline__ void cp16(unsigned dst, const void* src) {
    asm volatile("cp.async.cg.shared.global [%0], [%1], 16;" :: "r"(dst), "l"(src));
}
#define CP_COMMIT() asm volatile("cp.async.commit_group;" ::: "memory")
#define CP_WAIT0()  asm volatile("cp.async.wait_group 0;" ::: "memory")

__device__ __forceinline__ void split2(float a, float b, unsigned& h, unsigned& l) {
    __nv_bfloat16 ha = __float2bfloat16_rn(a), hb = __float2bfloat16_rn(b);
    float ra = a - __bfloat162float(ha), rb = b - __bfloat162float(hb);
    __nv_bfloat16 la = __float2bfloat16_rn(ra), lb = __float2bfloat16_rn(rb);
    h = (unsigned)__bfloat16_as_ushort(ha) | ((unsigned)__bfloat16_as_ushort(hb) << 16);
    l = (unsigned)__bfloat16_as_ushort(la) | ((unsigned)__bfloat16_as_ushort(lb) << 16);
}

// ---------- merged prep: blocks 0..63 -> w_down row; 64..87 -> w_up chunk ----------
__global__ void prep_all(const float* __restrict__ w_down, const float* __restrict__ b_down,
                         const float* __restrict__ gamma,  const float* __restrict__ beta,
                         const float* __restrict__ w_up) {
    int tid = threadIdx.x;
    if (blockIdx.x < 64) {
        int b = blockIdx.x;
        float s1 = 0.f, s2 = 0.f;
        for (int k = tid; k < ED; k += 256) {
            float w = w_down[b * ED + k];
            float wg = w * gamma[k];
            s1 += wg; s2 += beta[k] * w;
            __nv_bfloat16 hi = __float2bfloat16_rn(wg);
            __nv_bfloat16 lo = __float2bfloat16_rn(wg - __bfloat162float(hi));
            int idx = (k >> 6) * 4096 + b * 64 + (k & 63);
            g_wdh[idx] = hi; g_wdl[idx] = lo;
        }
        __shared__ float r1[256], r2[256];
        r1[tid] = s1; r2[tid] = s2; __syncthreads();
        for (int s = 128; s > 0; s >>= 1) {
            if (tid < s) { r1[tid] += r1[tid + s]; r2[tid] += r2[tid + s]; }
            __syncthreads();
        }
        if (tid == 0) { g_S1[b] = r1[0]; g_S2[b] = r2[0] + b_down[b]; }
    } else {
        int c = blockIdx.x - 64;
        for (int i = tid; i < 4096; i += 256) {
            int d = i >> 6, k = i & 63;
            float w = w_up[(c * 64 + d) * BN + k];
            __nv_bfloat16 hi = __float2bfloat16_rn(w);
            __nv_bfloat16 lo = __float2bfloat16_rn(w - __bfloat162float(hi));
            g_wuh[c * 4096 + i] = hi; g_wul[c * 4096 + i] = lo;
        }
    }
}

// ---------- main ----------
__global__ void __launch_bounds__(NTH, 2)
peft_mma(const float* __restrict__ x, const float* __restrict__ bup, float* __restrict__ out) {
    extern __shared__ char smraw[];
    unsigned rawa = (unsigned)__cvta_generic_to_shared(smraw);
    unsigned sa = (rawa + 1023) & ~1023u;
    char* sb = smraw + (sa - rawa);

    const int tid = threadIdx.x, warp = tid >> 5, lane = tid & 31;
    const int m = warp & 3, nh = warp >> 2;   // 4 m-tiles x 2 n-halves
    const long row0 = (long)blockIdx.x * MT;
    const int cr = tid >> 2, cs = tid & 3;    // conversion row / quarter

    float* BU  = (float*)(sb + O_BU);
    float* S1s = (float*)(sb + O_S1);
    float* S2s = (float*)(sb + O_S2);

    for (int i = tid; i < ED; i += NTH) BU[i] = bup[i];
    if (tid < BN) { S1s[tid] = g_S1[tid]; S2s[tid] = g_S2[tid]; }

    float sum = 0.f, sq = 0.f;

    // ---- prologue: stage Wd chunk 0 + convert X chunk 0 ----
    {
        #pragma unroll
        for (int s = 0; s < 2; ++s) {
            int i = tid * 2 + s, n = i >> 3, u = i & 7;
            cp16(sa + O_WB(0) + SWB(n, u),        g_wdh + n * 64 + u * 8);
            cp16(sa + O_WB(0) + 8192 + SWB(n, u), g_wdl + n * 64 + u * 8);
        }
        CP_COMMIT();
    }
    {
        const float* xp = x + (row0 + cr) * ED;
        char* xb = sb + O_XB(0);
        #pragma unroll
        for (int g = 0; g < 2; ++g) {
            float4 v0 = *(const float4*)(xp + cs * 16 + g * 8);
            float4 v1 = *(const float4*)(xp + cs * 16 + g * 8 + 4);
            sum += v0.x + v0.y + v0.z + v0.w + v1.x + v1.y + v1.z + v1.w;
            sq  += v0.x*v0.x + v0.y*v0.y + v0.z*v0.z + v0.w*v0.w
                 + v1.x*v1.x + v1.y*v1.y + v1.z*v1.z + v1.w*v1.w;
            unsigned h0,l0,h1,l1,h2,l2,h3,l3;
            split2(v0.x, v0.y, h0, l0); split2(v0.z, v0.w, h1, l1);
            split2(v1.x, v1.y, h2, l2); split2(v1.z, v1.w, h3, l3);
            unsigned off = SWB(cr, 2 * cs + g);
            *(uint4*)(xb + off)        = make_uint4(h0, h1, h2, h3);
            *(uint4*)(xb + 8192 + off) = make_uint4(l0, l1, l2, l3);
        }
    }

    // ================= GEMM1: H[64,64] = X * (gamma*Wd)^T =================
    float C1[4][4];
    #pragma unroll
    for (int nt = 0; nt < 4; ++nt)
        #pragma unroll
        for (int i = 0; i < 4; ++i) C1[nt][i] = 0.f;

    float4 pf0, pf1, pf2, pf3;
    for (int c = 0; c < NCH; ++c) {
        CP_WAIT0();
        __syncthreads();
        if (c < NCH - 1) {
            #pragma unroll
            for (int s = 0; s < 2; ++s) {
                int i = tid * 2 + s, n = i >> 3, u = i & 7;
                cp16(sa + O_WB((c + 1) & 1) + SWB(n, u),        g_wdh + (c + 1) * 4096 + n * 64 + u * 8);
                cp16(sa + O_WB((c + 1) & 1) + 8192 + SWB(n, u), g_wdl + (c + 1) * 4096 + n * 64 + u * 8);
            }
            CP_COMMIT();
            const float* xp = x + (row0 + cr) * ED + (c + 1) * 64 + cs * 16;
            pf0 = *(const float4*)(xp);
            pf1 = *(const float4*)(xp + 4);
            pf2 = *(const float4*)(xp + 8);
            pf3 = *(const float4*)(xp + 12);
        }
        unsigned xb = sa + O_XB(c & 1);
        unsigned wb = sa + O_WB(c & 1);
        const unsigned rowA = m * 16 + (lane & 15);
        #pragma unroll
        for (int kp = 0; kp < 2; ++kp) {
            unsigned ah0[4], al0[4], ah1[4], al1[4];
            unsigned uA0 = 4 * kp + (lane >> 4), uA1 = uA0 + 2;
            ldsm4(ah0, xb + SWB(rowA, uA0));
            ldsm4(al0, xb + 8192 + SWB(rowA, uA0));
            ldsm4(ah1, xb + SWB(rowA, uA1));
            ldsm4(al1, xb + 8192 + SWB(rowA, uA1));
            #pragma unroll
            for (int nt = 0; nt < 4; ++nt) {
                unsigned bh[4], bl[4];
                unsigned rowB = nh * 32 + nt * 8 + (lane & 7);
                unsigned uB = 4 * kp + (lane >> 3);
                ldsm4(bh, wb + SWB(rowB, uB));
                ldsm4(bl, wb + 8192 + SWB(rowB, uB));
                float* Cp = C1[nt];
                mma_bf(Cp, ah0, bh);     mma_bf(Cp, al0, bh);     mma_bf(Cp, ah0, bl);
                mma_bf(Cp, ah1, bh + 2); mma_bf(Cp, al1, bh + 2); mma_bf(Cp, ah1, bl + 2);
            }
        }
        if (c < NCH - 1) {
            char* xcb = sb + O_XB((c + 1) & 1);
            float4 vv[4] = {pf0, pf1, pf2, pf3};
            #pragma unroll
            for (int g = 0; g < 2; ++g) {
                float4 v0 = vv[g * 2], v1 = vv[g * 2 + 1];
                sum += v0.x + v0.y + v0.z + v0.w + v1.x + v1.y + v1.z + v1.w;
                sq  += v0.x*v0.x + v0.y*v0.y + v0.z*v0.z + v0.w*v0.w
                     + v1.x*v1.x + v1.y*v1.y + v1.z*v1.z + v1.w*v1.w;
                unsigned h0,l0,h1,l1,h2,l2,h3,l3;
                split2(v0.x, v0.y, h0, l0); split2(v0.z, v0.w, h1, l1);
                split2(v1.x, v1.y, h2, l2); split2(v1.z, v1.w, h3, l3);
                unsigned off = SWB(cr, 2 * cs + g);
                *(uint4*)(xcb + off)        = make_uint4(h0, h1, h2, h3);
                *(uint4*)(xcb + 8192 + off) = make_uint4(l0, l1, l2, l3);
            }
        }
    }

    // ---- LN stats: 4 lanes per row (consecutive) ----
    #pragma unroll
    for (int o = 1; o < 4; o <<= 1) {
        sum += __shfl_xor_sync(0xFFFFFFFFu, sum, o);
        sq  += __shfl_xor_sync(0xFFFFFFFFu, sq,  o);
    }
    if (cs == 0) {
        float mean = sum * (1.f / ED);
        ((float*)(sb + O_MS))[cr] = mean;
        ((float*)(sb + O_RS))[cr] = rsqrtf(sq * (1.f / ED) - mean * mean + 1e-5f);
    }
    __syncthreads();   // all ldsm of last chunk done; XB region now reusable as HRAW

    // ---- write C1 frags -> HRAW (overlaid on XB) ----
    {
        float* Hr = (float*)(sb + O_HRAW);
        #pragma unroll
        for (int nt = 0; nt < 4; ++nt)
            #pragma unroll
            for (int h = 0; h < 2; ++h) {
                int row = m * 16 + (lane >> 2) + h * 8;
                int col = nh * 32 + nt * 8 + 2 * (lane & 3);
                *(float2*)(Hr + row * 66 + col) = make_float2(C1[nt][h * 2], C1[nt][h * 2 + 1]);
            }
    }
    __syncthreads();

    // ---- LN finalize + GELU + bf16 split -> HH/HL ----
    {
        const float* Hr = (const float*)(sb + O_HRAW);
        float mean = ((float*)(sb + O_MS))[cr], rstd = ((float*)(sb + O_RS))[cr];
        #pragma unroll
        for (int g = 0; g < 2; ++g) {
            unsigned hw[4], lw[4];
            #pragma unroll
            for (int p = 0; p < 4; ++p) {
                int c0 = cs * 16 + g * 8 + p * 2;
                float v0 = Hr[cr * 66 + c0], v1 = Hr[cr * 66 + c0 + 1];
                float t0 = rstd * v0 - rstd * mean * S1s[c0]     + S2s[c0];
                float t1 = rstd * v1 - rstd * mean * S1s[c0 + 1] + S2s[c0 + 1];
                float g0 = 0.5f * t0 * (1.f + erff(t0 * 0.70710678118654752f));
                float g1 = 0.5f * t1 * (1.f + erff(t1 * 0.70710678118654752f));
                split2(g0, g1, hw[p], lw[p]);
            }
            unsigned off = SWB(cr, 2 * cs + g);
            *(uint4*)(sb + O_HH + off) = make_uint4(hw[0], hw[1], hw[2], hw[3]);
            *(uint4*)(sb + O_HL + off) = make_uint4(lw[0], lw[1], lw[2], lw[3]);
        }
    }
    __syncthreads();

    // ================= GEMM2: out = H * Wu^T + b_up + x =================
    const int dh = warp >> 2;   // d-half of each 64-col chunk
    unsigned Ah[4][4], Al[4][4];
    {
        unsigned rowA = m * 16 + (lane & 15);
        #pragma unroll
        for (int kk = 0; kk < 4; ++kk) {
            unsigned uA = 2 * kk + (lane >> 4);
            ldsm4(Ah[kk], sa + O_HH + SWB(rowA, uA));
            ldsm4(Al[kk], sa + O_HL + SWB(rowA, uA));
        }
    }
    {
        #pragma unroll
        for (int s = 0; s < 2; ++s) {
            int i = tid * 2 + s, d = i >> 3, u = i & 7;
            cp16(sa + O_WB(0) + SWB(d, u),        g_wuh + d * 64 + u * 8);
            cp16(sa + O_WB(0) + 8192 + SWB(d, u), g_wul + d * 64 + u * 8);
        }
        CP_COMMIT();
    }

    const long rgA = row0 + m * 16 + (lane >> 2);
    const long rgB = rgA + 8;
    float nacc0 = 0.f, nacc1 = 0.f;
    for (int c = 0; c < NCH; ++c) {
        CP_WAIT0();
        __syncthreads();
        if (c < NCH - 1) {
            #pragma unroll
            for (int s = 0; s < 2; ++s) {
                int i = tid * 2 + s, d = i >> 3, u = i & 7;
                cp16(sa + O_WB((c + 1) & 1) + SWB(d, u),        g_wuh + (c + 1) * 4096 + d * 64 + u * 8);
                cp16(sa + O_WB((c + 1) & 1) + 8192 + SWB(d, u), g_wul + (c + 1) * 4096 + d * 64 + u * 8);
            }
            CP_COMMIT();
        }
        // residual prefetch for this chunk
        float2 pfr[4][2];
        #pragma unroll
        for (int nt = 0; nt < 4; ++nt) {
            int col = c * 64 + dh * 32 + nt * 8 + 2 * (lane & 3);
            pfr[nt][0] = *(const float2*)(x + rgA * ED + col);
            pfr[nt][1] = *(const float2*)(x + rgB * ED + col);
        }
        unsigned wb = sa + O_WB(c & 1);
        #pragma unroll
        for (int nt = 0; nt < 4; ++nt) {
            float C2[4] = {0.f, 0.f, 0.f, 0.f};
            unsigned bh[2][4], bl[2][4];
            unsigned rowB = dh * 32 + nt * 8 + (lane & 7);
            #pragma unroll
            for (int kp = 0; kp < 2; ++kp) {
                unsigned uB = 4 * kp + (lane >> 3);
                ldsm4(bh[kp], wb + SWB(rowB, uB));
                ldsm4(bl[kp], wb + 8192 + SWB(rowB, uB));
            }
            #pragma unroll
            for (int kk = 0; kk < 4; ++kk) {
                const unsigned* bhp = &bh[kk >> 1][(kk & 1) * 2];
                const unsigned* blp = &bl[kk >> 1][(kk & 1) * 2];
                mma_bf(C2, Ah[kk], bhp);
                mma_bf(C2, Al[kk], bhp);
                mma_bf(C2, Ah[kk], blp);
            }
            int col = c * 64 + dh * 32 + nt * 8 + 2 * (lane & 3);
            {
                float v0 = C2[0] + pfr[nt][0].x + BU[col];
                float v1 = C2[1] + pfr[nt][0].y + BU[col + 1];
                nacc0 += v0 * v0 + v1 * v1;
                *(float2*)(out + rgA * ED + col) = make_float2(v0, v1);
            }
            {
                float v2 = C2[2] + pfr[nt][1].x + BU[col];
                float v3 = C2[3] + pfr[nt][1].y + BU[col + 1];
                nacc1 += v2 * v2 + v3 * v3;
                *(float2*)(out + rgB * ED + col) = make_float2(v2, v3);
            }
        }
    }

    // ---- row sumsq reduce -> inv norm ----
    {
        float* NR = (float*)(sb + O_NRM);
        NR[(m * 16 + (lane >> 2)) * 9 + dh * 4 + (lane & 3)]     = nacc0;
        NR[(m * 16 + 8 + (lane >> 2)) * 9 + dh * 4 + (lane & 3)] = nacc1;
    }
    __syncthreads();
    if (tid < MT) {
        const float* NR = (const float*)(sb + O_NRM) + tid * 9;
        float s = 0.f;
        #pragma unroll
        for (int i = 0; i < 8; ++i) s += NR[i];
        ((float*)(sb + O_INV))[tid] = 1.f / fmaxf(sqrtf(s), 1e-12f);
    }
    __syncthreads();

    // ---- rescale (L2-hot re-read of this CTA's output) ----
    {
        float sc = ((float*)(sb + O_INV))[cr];
        float4* op = (float4*)(out + (row0 + cr) * ED);
        #pragma unroll 8
        for (int j = 0; j < 96; ++j) {
            float4 v = op[j * 4 + cs];
            v.x *= sc; v.y *= sc; v.z *= sc; v.w *= sc;
            op[j * 4 + cs] = v;
        }
    }
}

extern "C" void kernel_launch(void* const* d_in, const int* in_sizes, int n_in,
                              void* d_out, int out_size) {
    const float* x      = (const float*)d_in[0];
    const float* w_down = (const float*)d_in[1];
    const float* b_down = (const float*)d_in[2];
    const float* w_up   = (const float*)d_in[3];
    const float* b_up   = (const float*)d_in[4];
    const float* gamma  = (const float*)d_in[5];
    const float* beta   = (const float*)d_in[6];
    float* out = (float*)d_out;

    const int n_rows = in_sizes[0] / ED;   // 32768

    cudaFuncSetAttribute(peft_mma, cudaFuncAttributeMaxDynamicSharedMemorySize, SMEM_REQ);

    prep_all<<<88, 256>>>(w_down, b_down, gamma, beta, w_up);
    peft_mma<<<n_rows / MT, NTH, SMEM_REQ>>>(x, b_up, out);
}